// round 1
// baseline (speedup 1.0000x reference)
#include <cuda_runtime.h>
#include <math.h>

// Problem constants (fixed by setup_inputs)
#define BB 64      // batch
#define TT 64      // time steps
#define AA 64      // action dim
#define HH 1024    // hidden
#define CC 16      // categories

// Scratch (device globals: allocation-free contract)
__device__ float g_tau[BB * HH];          // sinusoidal embedding per batch (256 KB)
__device__ float g_aemb[BB * TT * HH];    // layer-1 output (16 MB)
__device__ float g_h[BB * TT * HH];       // layer-2 output (16 MB)

// ---------------------------------------------------------------------------
// tau[b, j] = sin(t * f_j) for j<512, cos(t * f_{j-512}) for j>=512
// f_i = exp(-i * ln(10000)/512). timesteps is per-batch (constant over T).
// ---------------------------------------------------------------------------
__global__ void tau_kernel(const int* __restrict__ timesteps) {
    const int b = blockIdx.x;
    const float t = (float)timesteps[b];
    const float kexp = 9.210340371976184f / 512.0f;   // ln(10000)/half
    for (int j = threadIdx.x; j < HH; j += blockDim.x) {
        const int i = (j < 512) ? j : (j - 512);
        const float f = t * expf(-(float)i * kexp);
        g_tau[b * HH + j] = (j < 512) ? sinf(f) : cosf(f);
    }
}

// ---------------------------------------------------------------------------
// Shared SIMT GEMM geometry:
//   CTA tile: BM=64 rows (all T of one batch) x BN=128 cols, BK=8
//   128 threads as (tx 0..15, ty 0..7), each computes 8 rows x 8 cols.
//   Columns per thread are split (tx*4) and (64 + tx*4) -> conflict-free LDS.128.
// ---------------------------------------------------------------------------

// Layer 1: a_emb = actions @ W1[cat] + b1[cat]   (K = 64)
__global__ __launch_bounds__(128) void k1_kernel(
    const float* __restrict__ actions, const float* __restrict__ W1,
    const float* __restrict__ b1, const int* __restrict__ cat_ids)
{
    __shared__ __align__(16) float As[8][64];
    __shared__ __align__(16) float Bs[8][128];

    const int b   = blockIdx.y;
    const int n0  = blockIdx.x * 128;
    const int c   = cat_ids[b];
    const int tid = threadIdx.x;
    const int tx  = tid & 15, ty = tid >> 4;

    const float* Ap = actions + (size_t)b * TT * AA;          // 64 x 64
    const float* Bp = W1 + (size_t)c * AA * HH;               // 64 x 1024

    float acc[8][8];
    #pragma unroll
    for (int i = 0; i < 8; i++)
        #pragma unroll
        for (int j = 0; j < 8; j++) acc[i][j] = 0.0f;

    const int arow  = tid >> 1;
    const int ahalf = (tid & 1) * 4;

    for (int k0 = 0; k0 < AA; k0 += 8) {
        float4 av = *(const float4*)(Ap + (size_t)arow * AA + k0 + ahalf);
        As[ahalf + 0][arow] = av.x;  As[ahalf + 1][arow] = av.y;
        As[ahalf + 2][arow] = av.z;  As[ahalf + 3][arow] = av.w;
        #pragma unroll
        for (int i = 0; i < 2; i++) {
            const int lin = tid + i * 128;
            const int kk  = lin >> 5;
            const int nq  = (lin & 31) * 4;
            *(float4*)&Bs[kk][nq] =
                *(const float4*)(Bp + (size_t)(k0 + kk) * HH + n0 + nq);
        }
        __syncthreads();
        #pragma unroll
        for (int k = 0; k < 8; k++) {
            float a[8], bv[8];
            *(float4*)(a)      = *(const float4*)&As[k][ty * 8];
            *(float4*)(a + 4)  = *(const float4*)&As[k][ty * 8 + 4];
            *(float4*)(bv)     = *(const float4*)&Bs[k][tx * 4];
            *(float4*)(bv + 4) = *(const float4*)&Bs[k][64 + tx * 4];
            #pragma unroll
            for (int ii = 0; ii < 8; ii++)
                #pragma unroll
                for (int jj = 0; jj < 8; jj++)
                    acc[ii][jj] += a[ii] * bv[jj];
        }
        __syncthreads();
    }

    const float* bias = b1 + (size_t)c * HH + n0;
    float bv0[4], bv1[4];
    *(float4*)bv0 = *(const float4*)(bias + tx * 4);
    *(float4*)bv1 = *(const float4*)(bias + 64 + tx * 4);
    #pragma unroll
    for (int ii = 0; ii < 8; ii++) {
        float* orow = g_aemb + (size_t)(b * TT + ty * 8 + ii) * HH + n0;
        float4 o0 = make_float4(acc[ii][0] + bv0[0], acc[ii][1] + bv0[1],
                                acc[ii][2] + bv0[2], acc[ii][3] + bv0[3]);
        float4 o1 = make_float4(acc[ii][4] + bv1[0], acc[ii][5] + bv1[1],
                                acc[ii][6] + bv1[2], acc[ii][7] + bv1[3]);
        *(float4*)(orow + tx * 4)      = o0;
        *(float4*)(orow + 64 + tx * 4) = o1;
    }
}

// Layer 2: h = swish( a_emb @ W2_top[cat] + tau @ W2_bot[cat] + b2[cat] )
// The tau term is row-invariant within a CTA; accumulated once (k==ty split),
// reduced across ty via shared memory after the K loop.
__global__ __launch_bounds__(128) void k2_kernel(
    const float* __restrict__ W2, const float* __restrict__ b2,
    const int* __restrict__ cat_ids)
{
    __shared__ __align__(16) float As[8][64];
    __shared__ __align__(16) float Bs[8][128];
    __shared__ __align__(16) float Bsb[8][128];
    __shared__ float taus[8];
    __shared__ float red[8][128];

    const int b   = blockIdx.y;
    const int n0  = blockIdx.x * 128;
    const int c   = cat_ids[b];
    const int tid = threadIdx.x;
    const int tx  = tid & 15, ty = tid >> 4;

    const float* Ap   = g_aemb + (size_t)b * TT * HH;
    const float* Btop = W2 + (size_t)c * 2 * HH * HH;        // rows 0..1023
    const float* Bbot = Btop + (size_t)HH * HH;              // rows 1024..2047

    float acc[8][8];
    #pragma unroll
    for (int i = 0; i < 8; i++)
        #pragma unroll
        for (int j = 0; j < 8; j++) acc[i][j] = 0.0f;
    float tacc[8];
    #pragma unroll
    for (int j = 0; j < 8; j++) tacc[j] = 0.0f;

    const int arow  = tid >> 1;
    const int ahalf = (tid & 1) * 4;

    for (int k0 = 0; k0 < HH; k0 += 8) {
        if (tid < 8) taus[tid] = g_tau[b * HH + k0 + tid];
        float4 av = *(const float4*)(Ap + (size_t)arow * HH + k0 + ahalf);
        As[ahalf + 0][arow] = av.x;  As[ahalf + 1][arow] = av.y;
        As[ahalf + 2][arow] = av.z;  As[ahalf + 3][arow] = av.w;
        #pragma unroll
        for (int i = 0; i < 2; i++) {
            const int lin = tid + i * 128;
            const int kk  = lin >> 5;
            const int nq  = (lin & 31) * 4;
            *(float4*)&Bs[kk][nq] =
                *(const float4*)(Btop + (size_t)(k0 + kk) * HH + n0 + nq);
            *(float4*)&Bsb[kk][nq] =
                *(const float4*)(Bbot + (size_t)(k0 + kk) * HH + n0 + nq);
        }
        __syncthreads();
        #pragma unroll
        for (int k = 0; k < 8; k++) {
            float a[8], bv[8];
            *(float4*)(a)      = *(const float4*)&As[k][ty * 8];
            *(float4*)(a + 4)  = *(const float4*)&As[k][ty * 8 + 4];
            *(float4*)(bv)     = *(const float4*)&Bs[k][tx * 4];
            *(float4*)(bv + 4) = *(const float4*)&Bs[k][64 + tx * 4];
            #pragma unroll
            for (int ii = 0; ii < 8; ii++)
                #pragma unroll
                for (int jj = 0; jj < 8; jj++)
                    acc[ii][jj] += a[ii] * bv[jj];
        }
        {   // tau projection: this thread handles k == ty
            const float tv = taus[ty];
            float bv[8];
            *(float4*)(bv)     = *(const float4*)&Bsb[ty][tx * 4];
            *(float4*)(bv + 4) = *(const float4*)&Bsb[ty][64 + tx * 4];
            #pragma unroll
            for (int j = 0; j < 8; j++) tacc[j] += tv * bv[j];
        }
        __syncthreads();
    }

    // Reduce tau partials across ty
    #pragma unroll
    for (int j = 0; j < 4; j++) {
        red[ty][tx * 4 + j]      = tacc[j];
        red[ty][64 + tx * 4 + j] = tacc[4 + j];
    }
    __syncthreads();
    float tsum[8];
    #pragma unroll
    for (int j = 0; j < 4; j++) {
        float s0 = 0.0f, s1 = 0.0f;
        #pragma unroll
        for (int q = 0; q < 8; q++) {
            s0 += red[q][tx * 4 + j];
            s1 += red[q][64 + tx * 4 + j];
        }
        tsum[j] = s0;  tsum[4 + j] = s1;
    }

    const float* bias = b2 + (size_t)c * HH + n0;
    float bv0[4], bv1[4];
    *(float4*)bv0 = *(const float4*)(bias + tx * 4);
    *(float4*)bv1 = *(const float4*)(bias + 64 + tx * 4);
    #pragma unroll
    for (int ii = 0; ii < 8; ii++) {
        float* orow = g_h + (size_t)(b * TT + ty * 8 + ii) * HH + n0;
        float o[8];
        #pragma unroll
        for (int jj = 0; jj < 8; jj++) {
            const float bias_j = (jj < 4) ? bv0[jj] : bv1[jj - 4];
            const float pre = acc[ii][jj] + tsum[jj] + bias_j;
            const float sig = 1.0f / (1.0f + expf(-pre));
            o[jj] = pre * sig;
        }
        *(float4*)(orow + tx * 4)      = make_float4(o[0], o[1], o[2], o[3]);
        *(float4*)(orow + 64 + tx * 4) = make_float4(o[4], o[5], o[6], o[7]);
    }
}

// Layer 3: out = h @ W3[cat] + b3[cat]   (K = 1024)
__global__ __launch_bounds__(128) void k3_kernel(
    const float* __restrict__ W3, const float* __restrict__ b3,
    const int* __restrict__ cat_ids, float* __restrict__ out)
{
    __shared__ __align__(16) float As[8][64];
    __shared__ __align__(16) float Bs[8][128];

    const int b   = blockIdx.y;
    const int n0  = blockIdx.x * 128;
    const int c   = cat_ids[b];
    const int tid = threadIdx.x;
    const int tx  = tid & 15, ty = tid >> 4;

    const float* Ap = g_h + (size_t)b * TT * HH;
    const float* Bp = W3 + (size_t)c * HH * HH;

    float acc[8][8];
    #pragma unroll
    for (int i = 0; i < 8; i++)
        #pragma unroll
        for (int j = 0; j < 8; j++) acc[i][j] = 0.0f;

    const int arow  = tid >> 1;
    const int ahalf = (tid & 1) * 4;

    for (int k0 = 0; k0 < HH; k0 += 8) {
        float4 av = *(const float4*)(Ap + (size_t)arow * HH + k0 + ahalf);
        As[ahalf + 0][arow] = av.x;  As[ahalf + 1][arow] = av.y;
        As[ahalf + 2][arow] = av.z;  As[ahalf + 3][arow] = av.w;
        #pragma unroll
        for (int i = 0; i < 2; i++) {
            const int lin = tid + i * 128;
            const int kk  = lin >> 5;
            const int nq  = (lin & 31) * 4;
            *(float4*)&Bs[kk][nq] =
                *(const float4*)(Bp + (size_t)(k0 + kk) * HH + n0 + nq);
        }
        __syncthreads();
        #pragma unroll
        for (int k = 0; k < 8; k++) {
            float a[8], bv[8];
            *(float4*)(a)      = *(const float4*)&As[k][ty * 8];
            *(float4*)(a + 4)  = *(const float4*)&As[k][ty * 8 + 4];
            *(float4*)(bv)     = *(const float4*)&Bs[k][tx * 4];
            *(float4*)(bv + 4) = *(const float4*)&Bs[k][64 + tx * 4];
            #pragma unroll
            for (int ii = 0; ii < 8; ii++)
                #pragma unroll
                for (int jj = 0; jj < 8; jj++)
                    acc[ii][jj] += a[ii] * bv[jj];
        }
        __syncthreads();
    }

    const float* bias = b3 + (size_t)c * HH + n0;
    float bv0[4], bv1[4];
    *(float4*)bv0 = *(const float4*)(bias + tx * 4);
    *(float4*)bv1 = *(const float4*)(bias + 64 + tx * 4);
    #pragma unroll
    for (int ii = 0; ii < 8; ii++) {
        float* orow = out + (size_t)(b * TT + ty * 8 + ii) * HH + n0;
        float4 o0 = make_float4(acc[ii][0] + bv0[0], acc[ii][1] + bv0[1],
                                acc[ii][2] + bv0[2], acc[ii][3] + bv0[3]);
        float4 o1 = make_float4(acc[ii][4] + bv1[0], acc[ii][5] + bv1[1],
                                acc[ii][6] + bv1[2], acc[ii][7] + bv1[3]);
        *(float4*)(orow + tx * 4)      = o0;
        *(float4*)(orow + 64 + tx * 4) = o1;
    }
}

// ---------------------------------------------------------------------------
// Harness entry. Input order (metadata): actions, timesteps, cat_ids,
// W1, b1, W2, b2, W3, b3. Output: (64, 64, 1024) fp32.
// ---------------------------------------------------------------------------
extern "C" void kernel_launch(void* const* d_in, const int* in_sizes, int n_in,
                              void* d_out, int out_size)
{
    const float* actions   = (const float*)d_in[0];
    const int*   timesteps = (const int*)  d_in[1];
    const int*   cat_ids   = (const int*)  d_in[2];
    const float* W1        = (const float*)d_in[3];
    const float* b1        = (const float*)d_in[4];
    const float* W2        = (const float*)d_in[5];
    const float* b2        = (const float*)d_in[6];
    const float* W3        = (const float*)d_in[7];
    const float* b3        = (const float*)d_in[8];
    float* out = (float*)d_out;

    tau_kernel<<<BB, 256>>>(timesteps);

    dim3 grid(HH / 128, BB);   // (8 col-tiles, 64 batches)
    k1_kernel<<<grid, 128>>>(actions, W1, b1, cat_ids);
    k2_kernel<<<grid, 128>>>(W2, b2, cat_ids);
    k3_kernel<<<grid, 128>>>(W3, b3, cat_ids, out);
}

// round 4
// speedup vs baseline: 1.4671x; 1.4671x over previous
#include <cuda_runtime.h>
#include <cuda_bf16.h>
#include <cstdint>
#include <string.h>
#include <math.h>

#define BB 64
#define TT 64
#define AA 64
#define HH 1024

// ---------------- device scratch (allocation-free contract) ----------------
__device__ __align__(16) __nv_bfloat16 g_act_hi[BB * TT * AA];
__device__ __align__(16) __nv_bfloat16 g_act_lo[BB * TT * AA];
__device__ __align__(16) __nv_bfloat16 g_x_hi[BB * TT * 2 * HH];
__device__ __align__(16) __nv_bfloat16 g_x_lo[BB * TT * 2 * HH];
__device__ __align__(16) __nv_bfloat16 g_h_hi[BB * TT * HH];
__device__ __align__(16) __nv_bfloat16 g_h_lo[BB * TT * HH];

// ---------------- helpers ----------------
__device__ __forceinline__ uint32_t smem_u32(const void* p) {
    uint32_t a;
    asm("{ .reg .u64 t; cvta.to.shared.u64 t, %1; cvt.u32.u64 %0, t; }" : "=r"(a) : "l"(p));
    return a;
}

__device__ __forceinline__ void ldsm_x4(uint32_t* r, uint32_t addr) {
    asm volatile("ldmatrix.sync.aligned.m8n8.x4.shared.b16 {%0,%1,%2,%3}, [%4];"
                 : "=r"(r[0]), "=r"(r[1]), "=r"(r[2]), "=r"(r[3]) : "r"(addr));
}
__device__ __forceinline__ void ldsm_x4t(uint32_t* r, uint32_t addr) {
    asm volatile("ldmatrix.sync.aligned.m8n8.x4.trans.shared.b16 {%0,%1,%2,%3}, [%4];"
                 : "=r"(r[0]), "=r"(r[1]), "=r"(r[2]), "=r"(r[3]) : "r"(addr));
}
__device__ __forceinline__ void mma_bf16(float* d, const uint32_t* a, const uint32_t* bfr) {
    asm volatile("mma.sync.aligned.m16n8k16.row.col.f32.bf16.bf16.f32 "
                 "{%0,%1,%2,%3}, {%4,%5,%6,%7}, {%8,%9}, {%0,%1,%2,%3};"
                 : "+f"(d[0]), "+f"(d[1]), "+f"(d[2]), "+f"(d[3])
                 : "r"(a[0]), "r"(a[1]), "r"(a[2]), "r"(a[3]), "r"(bfr[0]), "r"(bfr[1]));
}

__device__ __forceinline__ uint32_t bits2(__nv_bfloat162 v) {
    uint32_t w; memcpy(&w, &v, 4); return w;
}
__device__ __forceinline__ void split2(float v, __nv_bfloat16& h, __nv_bfloat16& l) {
    h = __float2bfloat16(v);
    l = __float2bfloat16(v - __bfloat162float(h));
}
// 8 consecutive floats -> hi uint4 + lo uint4 (bf16 pairs)
__device__ __forceinline__ void cvt8(float4 u, float4 v, uint4& hi, uint4& lo) {
    float f[8] = {u.x, u.y, u.z, u.w, v.x, v.y, v.z, v.w};
    uint32_t h[4], l[4];
    #pragma unroll
    for (int i = 0; i < 4; i++) {
        float a = f[2 * i], b = f[2 * i + 1];
        __nv_bfloat162 hh = __floats2bfloat162_rn(a, b);
        float ra = a - __bfloat162float(__low2bfloat16(hh));
        float rb = b - __bfloat162float(__high2bfloat16(hh));
        __nv_bfloat162 ll = __floats2bfloat162_rn(ra, rb);
        h[i] = bits2(hh); l[i] = bits2(ll);
    }
    hi = make_uint4(h[0], h[1], h[2], h[3]);
    lo = make_uint4(l[0], l[1], l[2], l[3]);
}

// ---------------- prep kernels ----------------
__global__ void prep_act_kernel(const float* __restrict__ actions) {
    const int b = blockIdx.x;
    for (int i = threadIdx.x; i < TT * AA; i += blockDim.x) {
        float v = actions[b * TT * AA + i];
        __nv_bfloat16 h, l; split2(v, h, l);
        g_act_hi[b * TT * AA + i] = h;
        g_act_lo[b * TT * AA + i] = l;
    }
}

__global__ void tau_fill_kernel(const int* __restrict__ timesteps) {
    __shared__ uint32_t hi2[512], lo2[512];
    const int b = blockIdx.x;
    const float t = (float)timesteps[b];
    const float kexp = 9.210340371976184f / 512.0f;
    for (int p = threadIdx.x; p < 512; p += blockDim.x) {
        int j0 = 2 * p, j1 = 2 * p + 1;
        int i0 = (j0 < 512) ? j0 : (j0 - 512);
        int i1 = (j1 < 512) ? j1 : (j1 - 512);
        float f0 = t * expf(-(float)i0 * kexp);
        float f1 = t * expf(-(float)i1 * kexp);
        float v0 = (j0 < 512) ? sinf(f0) : cosf(f0);
        float v1 = (j1 < 512) ? sinf(f1) : cosf(f1);
        __nv_bfloat16 h0, l0, h1, l1; split2(v0, h0, l0); split2(v1, h1, l1);
        hi2[p] = (uint32_t)__bfloat16_as_ushort(h0) | ((uint32_t)__bfloat16_as_ushort(h1) << 16);
        lo2[p] = (uint32_t)__bfloat16_as_ushort(l0) | ((uint32_t)__bfloat16_as_ushort(l1) << 16);
    }
    __syncthreads();
    for (int tt = 0; tt < TT; tt++) {
        uint32_t* dh = (uint32_t*)(g_x_hi + ((size_t)(b * TT + tt) * 2 * HH + HH));
        uint32_t* dl = (uint32_t*)(g_x_lo + ((size_t)(b * TT + tt) * 2 * HH + HH));
        for (int i = threadIdx.x; i < 512; i += blockDim.x) {
            dh[i] = hi2[i];
            dl[i] = lo2[i];
        }
    }
}

// ---------------- main GEMM: mma.sync bf16, 3-pass hi/lo split ----------------
// CTA: 256 thr (8 warps 2Mx4N). Tile M=64 tokens x N=128 feats. K-stage 32.
// SMEM stage (24KB): A (64 rows x 128B: [4 hi chunks | 4 lo chunks] per row),
//                    Bhi (32 rows x 256B), Blo (32 rows x 256B). x2 buffers.
// Swizzle: 16B-chunk index XOR (row & 7).
// mode 0: K=64   X=g_act -> g_x[:, :1024] (+bias)
// mode 1: K=2048 X=g_x   -> g_h (swish(+bias))
// mode 2: K=1024 X=g_h   -> fp32 out (+bias)

__global__ __launch_bounds__(256) void gemm_kernel(
    const float* __restrict__ W, const float* __restrict__ bias,
    const int* __restrict__ cat_ids, float* __restrict__ outf, int mode)
{
    __shared__ __align__(1024) char smem[49152];
    const int tid = threadIdx.x;
    const int wid = tid >> 5, lane = tid & 31;
    const int b = blockIdx.y;
    const int n0 = blockIdx.x * 128;
    const int c = cat_ids[b];

    int KTOT, ldb;
    const __nv_bfloat16 *Xhi, *Xlo;
    if (mode == 0)      { KTOT = 64;   ldb = 64;   Xhi = g_act_hi; Xlo = g_act_lo; }
    else if (mode == 1) { KTOT = 2048; ldb = 2048; Xhi = g_x_hi;   Xlo = g_x_lo; }
    else                { KTOT = 1024; ldb = 1024; Xhi = g_h_hi;   Xlo = g_h_lo; }

    const float* Wc = W + (size_t)c * KTOT * HH;
    const uint32_t sbase = smem_u32(smem);

    // ---- staging maps ----
    const int m_a = tid >> 2, ck_a = tid & 3;              // A: 1 hi + 1 lo chunk
    const size_t gA = (size_t)(b * TT + m_a) * ldb + ck_a * 8;
    const int kB0 = tid >> 4, cB0 = tid & 15;              // B: rows kB0, kB0+16
    const int kB1 = kB0 + 16;

    uint4 sAhi, sAlo;
    float4 sB[4];

    float acc[2][4][4];
    #pragma unroll
    for (int i = 0; i < 2; i++)
        #pragma unroll
        for (int j = 0; j < 4; j++)
            #pragma unroll
            for (int q = 0; q < 4; q++) acc[i][j][q] = 0.0f;

    const int nst = KTOT >> 5;

    auto ldg = [&](int k0) {
        sAhi = *(const uint4*)(Xhi + gA + k0);
        sAlo = *(const uint4*)(Xlo + gA + k0);
        const float* wp0 = Wc + (size_t)(k0 + kB0) * HH + n0 + cB0 * 8;
        const float* wp1 = Wc + (size_t)(k0 + kB1) * HH + n0 + cB0 * 8;
        sB[0] = *(const float4*)wp0;  sB[1] = *(const float4*)(wp0 + 4);
        sB[2] = *(const float4*)wp1;  sB[3] = *(const float4*)(wp1 + 4);
    };
    auto sts = [&](int buf) {
        char* st = smem + buf * 24576;
        const uint32_t ra = (uint32_t)m_a * 128;
        *(uint4*)(st + ra + (uint32_t)((ck_a ^ (m_a & 7)) * 16))       = sAhi;
        *(uint4*)(st + ra + (uint32_t)(((4 + ck_a) ^ (m_a & 7)) * 16)) = sAlo;
        uint4 h0, l0, h1, l1;
        cvt8(sB[0], sB[1], h0, l0);
        cvt8(sB[2], sB[3], h1, l1);
        const uint32_t sw = (uint32_t)((cB0 ^ (kB0 & 7)) * 16);
        *(uint4*)(st + 8192  + (uint32_t)kB0 * 256 + sw) = h0;
        *(uint4*)(st + 16384 + (uint32_t)kB0 * 256 + sw) = l0;
        *(uint4*)(st + 8192  + (uint32_t)kB1 * 256 + sw) = h1;
        *(uint4*)(st + 16384 + (uint32_t)kB1 * 256 + sw) = l1;
    };

    const int wm = wid >> 2, wn = wid & 3;
    const int lr = lane & 15, lc = lane >> 4;

    auto compute = [&](int buf) {
        const uint32_t Ab  = sbase + buf * 24576;
        const uint32_t Bhb = Ab + 8192;
        const uint32_t Blb = Ab + 16384;
        #pragma unroll
        for (int kk = 0; kk < 2; kk++) {
            uint32_t ah[2][4], al[2][4], bh[2][4], bl[2][4];
            #pragma unroll
            for (int mt = 0; mt < 2; mt++) {
                const int r = wm * 32 + mt * 16 + lr;
                const int cb = kk * 2 + lc;
                ldsm_x4(ah[mt], Ab + (uint32_t)r * 128 + (uint32_t)((cb       ^ (r & 7)) * 16));
                ldsm_x4(al[mt], Ab + (uint32_t)r * 128 + (uint32_t)(((cb + 4) ^ (r & 7)) * 16));
            }
            #pragma unroll
            for (int g = 0; g < 2; g++) {
                const int kr = kk * 16 + lr;
                const uint32_t cb = (uint32_t)(((wn * 4 + g * 2 + lc) ^ (kr & 7)) * 16);
                ldsm_x4t(bh[g], Bhb + (uint32_t)kr * 256 + cb);
                ldsm_x4t(bl[g], Blb + (uint32_t)kr * 256 + cb);
            }
            #pragma unroll
            for (int mt = 0; mt < 2; mt++)
                #pragma unroll
                for (int n8 = 0; n8 < 4; n8++) {
                    const int g = n8 >> 1, hf = (n8 & 1) * 2;
                    mma_bf16(acc[mt][n8], ah[mt], &bh[g][hf]);
                    mma_bf16(acc[mt][n8], al[mt], &bh[g][hf]);
                    mma_bf16(acc[mt][n8], ah[mt], &bl[g][hf]);
                }
        }
    };

    // ---- pipelined main loop ----
    ldg(0);
    sts(0);
    __syncthreads();
    for (int s = 0; s < nst; s++) {
        if (s + 1 < nst) ldg((s + 1) * 32);
        compute(s & 1);
        if (s + 1 < nst) sts((s + 1) & 1);
        __syncthreads();
    }

    // ---- epilogue ----
    const int r4 = lane >> 2, c2 = (lane & 3) * 2;
    const float* bp = bias + (size_t)c * HH + n0 + wn * 32;

    if (mode == 2) {
        #pragma unroll
        for (int mt = 0; mt < 2; mt++)
            #pragma unroll
            for (int n8 = 0; n8 < 4; n8++) {
                const int row = wm * 32 + mt * 16 + r4;
                const int col = wn * 32 + n8 * 8 + c2;
                const float b0 = bp[n8 * 8 + c2], b1 = bp[n8 * 8 + c2 + 1];
                float* o0 = outf + (size_t)(b * TT + row) * HH + n0 + col;
                float* o1 = outf + (size_t)(b * TT + row + 8) * HH + n0 + col;
                *(float2*)o0 = make_float2(acc[mt][n8][0] + b0, acc[mt][n8][1] + b1);
                *(float2*)o1 = make_float2(acc[mt][n8][2] + b0, acc[mt][n8][3] + b1);
            }
    } else {
        const int ldo = (mode == 0) ? 2 * HH : HH;
        __nv_bfloat16* Ohi = (mode == 0) ? g_x_hi : g_h_hi;
        __nv_bfloat16* Olo = (mode == 0) ? g_x_lo : g_h_lo;
        #pragma unroll
        for (int mt = 0; mt < 2; mt++)
            #pragma unroll
            for (int n8 = 0; n8 < 4; n8++) {
                const int col = wn * 32 + n8 * 8 + c2;
                const float b0 = bp[n8 * 8 + c2], b1 = bp[n8 * 8 + c2 + 1];
                #pragma unroll
                for (int hrow = 0; hrow < 2; hrow++) {
                    const int row = wm * 32 + mt * 16 + r4 + hrow * 8;
                    float va = acc[mt][n8][hrow * 2 + 0] + b0;
                    float vb = acc[mt][n8][hrow * 2 + 1] + b1;
                    if (mode == 1) {
                        va = va / (1.0f + expf(-va));
                        vb = vb / (1.0f + expf(-vb));
                    }
                    __nv_bfloat162 hh = __floats2bfloat162_rn(va, vb);
                    float ra = va - __bfloat162float(__low2bfloat16(hh));
                    float rb = vb - __bfloat162float(__high2bfloat16(hh));
                    __nv_bfloat162 ll = __floats2bfloat162_rn(ra, rb);
                    const size_t o = (size_t)(b * TT + row) * ldo + n0 + col;
                    *(uint32_t*)(Ohi + o) = bits2(hh);
                    *(uint32_t*)(Olo + o) = bits2(ll);
                }
            }
    }
}

// ---------------- harness entry ----------------
extern "C" void kernel_launch(void* const* d_in, const int* in_sizes, int n_in,
                              void* d_out, int out_size)
{
    const float* actions   = (const float*)d_in[0];
    const int*   timesteps = (const int*)  d_in[1];
    const int*   cat_ids   = (const int*)  d_in[2];
    const float* W1        = (const float*)d_in[3];
    const float* b1        = (const float*)d_in[4];
    const float* W2        = (const float*)d_in[5];
    const float* b2        = (const float*)d_in[6];
    const float* W3        = (const float*)d_in[7];
    const float* b3        = (const float*)d_in[8];
    float* out = (float*)d_out;

    prep_act_kernel<<<BB, 256>>>(actions);
    tau_fill_kernel<<<BB, 256>>>(timesteps);

    dim3 grid(HH / 128, BB);   // 8 feature-tiles x 64 batches
    gemm_kernel<<<grid, 256>>>(W1, b1, cat_ids, nullptr, 0);
    gemm_kernel<<<grid, 256>>>(W2, b2, cat_ids, nullptr, 1);
    gemm_kernel<<<grid, 256>>>(W3, b3, cat_ids, out, 2);
}